// round 9
// baseline (speedup 1.0000x reference)
#include <cuda_runtime.h>
#include <cstdint>

// Ragged position fill (vLLM prepare-inputs style), balanced-tile version.
//   pos[t]      = nct[idx_mapping[req(t)]] + (t - qsl[req(t)])   (= base + t)
//   seq_lens[r] = nct[idx_mapping[r]] + (qsl[r+1]-qsl[r]) for r<num_reqs, else 0
// d_out = [ pos (num_tokens) | seq_lens (max_num_reqs) ]  as FLOAT32.
//
// R9 design: R7/R8 proved block-per-request is serialization-bound (issue
// halved, duration unchanged). Now each block owns a fixed 4096-token tile:
// binary-search qsl for the tile's first request, then stream spans. Work is
// perfectly balanced; the ~2 span-boundary gathers per tile hide across waves.

#define TILE_TOKENS 4096
#define SEQ_BLOCKS 64

__global__ __launch_bounds__(256) void tile_fill_kernel(
    const int* __restrict__ idx_mapping,
    const int* __restrict__ qsl,
    const int* __restrict__ nct,
    float* __restrict__ out_base,
    int num_reqs, int max_num_reqs,
    int ntile_blocks,
    long long out_size)
{
    const int num_tokens = __ldg(&qsl[num_reqs]);   // true token count (device)

    if ((int)blockIdx.x >= ntile_blocks) {
        // ---- seq_lens blocks ----
        const long long need = (long long)num_tokens + (long long)max_num_reqs;
        if (out_size != need && out_size != 4 * need) return;
        float* seq_out = out_base + num_tokens;
        const int nthreads = SEQ_BLOCKS * 256;
        int i = ((int)blockIdx.x - ntile_blocks) * 256 + (int)threadIdx.x;
        for (; i < max_num_reqs; i += nthreads) {
            int v = 0;
            if (i < num_reqs) {
                int qlen = __ldg(&qsl[i + 1]) - __ldg(&qsl[i]);
                v = __ldg(&nct[__ldg(&idx_mapping[i])]) + qlen;
            }
            seq_out[i] = (float)v;
        }
        return;
    }

    // ---- pos tile blocks: fixed 4096-token tiles ----
    int t0 = (int)blockIdx.x * TILE_TOKENS;
    if (t0 >= num_tokens) return;                    // over-provisioned grid
    int t_end = t0 + TILE_TOKENS;
    if (t_end > num_tokens) t_end = num_tokens;

    // binary search: r = last index with qsl[r] <= t0  (qsl[r+1] > t0)
    int lo = 0, hi = num_reqs;
    while (lo + 1 < hi) {
        int mid = (lo + hi) >> 1;
        if (__ldg(&qsl[mid]) <= t0) lo = mid; else hi = mid;
    }
    int r = lo;
    int span_end = __ldg(&qsl[r + 1]);

    // walk spans covering [t0, t_end)
    while (t0 < t_end) {
        // base for request r (dependent gather; next iteration's loads
        // overlap with this span's stores via other resident blocks)
        const int base = __ldg(&nct[__ldg(&idx_mapping[r])]) - __ldg(&qsl[r]);
        int s1 = span_end < t_end ? span_end : t_end;

        if (s1 > t0) {
            const int a0 = (t0 + 3) & ~3;
            const int a1 = s1 & ~3;
            if (a1 > a0) {
                int t = t0 + (int)threadIdx.x;
                if (t < a0) out_base[t] = (float)(base + t);

                const int nv4 = (a1 - a0) >> 2;
                float4* vp = reinterpret_cast<float4*>(out_base + a0);
                for (int v = (int)threadIdx.x; v < nv4; v += 256) {
                    int tv = a0 + (v << 2) + base;
                    vp[v] = make_float4((float)tv, (float)(tv + 1),
                                        (float)(tv + 2), (float)(tv + 3));
                }

                int tt = a1 + (int)threadIdx.x;
                if (tt < s1) out_base[tt] = (float)(base + tt);
            } else {
                for (int t = t0 + (int)threadIdx.x; t < s1; t += 256)
                    out_base[t] = (float)(base + t);
            }
            t0 = s1;
        }
        if (t0 >= t_end) break;
        r++;
        span_end = __ldg(&qsl[r + 1]);
    }
}

extern "C" void kernel_launch(void* const* d_in, const int* in_sizes, int n_in,
                              void* d_out, int out_size) {
    // stable sort of input indices by size (ascending)
    int ord[32];
    int n = n_in > 32 ? 32 : n_in;
    for (int i = 0; i < n; i++) ord[i] = i;
    for (int i = 1; i < n; i++) {
        int key = ord[i];
        int j = i - 1;
        while (j >= 0 && in_sizes[ord[j]] > in_sizes[key]) {
            ord[j + 1] = ord[j];
            j--;
        }
        ord[j + 1] = key;
    }
    // rank mapping: ord[0]=idx_mapping, ord[1]=qsl, ord[2]=num_computed_tokens
    int idx_i = ord[0];
    int qsl_i = (n > 1) ? ord[1] : ord[0];
    int nct_i = (n > 2) ? ord[2] : qsl_i;

    const int* idx_mapping = (const int*)d_in[idx_i];
    const int* qsl         = (const int*)d_in[qsl_i];
    const int* nct         = (const int*)d_in[nct_i];

    // unit: size(qsl) - size(idx) == bytes-per-element of in_sizes
    long long unit = (long long)in_sizes[qsl_i] - (long long)in_sizes[idx_i];
    if (unit <= 0) unit = 1;
    const int num_reqs     = (int)(in_sizes[idx_i] / unit);
    const int max_num_reqs = (int)(in_sizes[nct_i] / unit);

    // upper bound on token count from out_size (works for elements or bytes;
    // excess tile blocks early-exit against the device-read num_tokens)
    long long ub_tokens = (long long)out_size;
    if (ub_tokens < 1) ub_tokens = 1;
    int ntile_blocks = (int)((ub_tokens + TILE_TOKENS - 1) / TILE_TOKENS);

    tile_fill_kernel<<<ntile_blocks + SEQ_BLOCKS, 256>>>(
        idx_mapping, qsl, nct, (float*)d_out,
        num_reqs, max_num_reqs, ntile_blocks, (long long)out_size);
}

// round 10
// speedup vs baseline: 1.3004x; 1.3004x over previous
#include <cuda_runtime.h>
#include <cstdint>

// Ragged position fill (vLLM prepare-inputs style), persistent single-wave
// version with software-pipelined metadata prefetch.
//   pos[t]      = nct[idx_mapping[req(t)]] + (t - qsl[req(t)])   (= base + t)
//   seq_lens[r] = nct[idx_mapping[r]] + (qsl[r+1]-qsl[r]) for r<num_reqs, else 0
// d_out = [ pos (num_tokens) | seq_lens (max_num_reqs) ]  as FLOAT32.
//
// R10 design: R7/R8 showed ~7 serial CTA waves each paying a dependent
// qsl/idx->nct chain with almost no payload to hide it. Now POS_BLOCKS=1216
// blocks (one resident wave) each own requests {b, b+1216, ...} and prefetch
// request k+1's metadata before streaming request k's stores, so the gather
// chain overlaps with store issue instead of serializing.

#define SEQ_BLOCKS 64
#define POS_BLOCKS 1216

__device__ __forceinline__ unsigned long long addf32x2(unsigned long long a,
                                                       unsigned long long b) {
    unsigned long long r;
    asm("add.rn.f32x2 %0, %1, %2;" : "=l"(r) : "l"(a), "l"(b));
    return r;
}
__device__ __forceinline__ unsigned long long packf2(float lo, float hi) {
    unsigned long long r;
    asm("mov.b64 %0, {%1, %2};" : "=l"(r) : "f"(lo), "f"(hi));
    return r;
}

__global__ __launch_bounds__(256) void fused_fill_kernel(
    const int* __restrict__ idx_mapping,
    const int* __restrict__ qsl,
    const int* __restrict__ nct,
    float* __restrict__ out_base,
    int num_reqs, int max_num_reqs,
    long long out_size)
{
    const int bid = (int)blockIdx.x;

    if (bid >= POS_BLOCKS) {
        // ---- seq_lens blocks: cover [0, max_num_reqs) ----
        const long long num_tokens = (long long)__ldg(&qsl[num_reqs]);
        const long long need = num_tokens + (long long)max_num_reqs;
        if (out_size != need && out_size != 4 * need) return;
        float* seq_out = out_base + num_tokens;
        const int nthreads = SEQ_BLOCKS * 256;
        int i = (bid - POS_BLOCKS) * 256 + (int)threadIdx.x;
        for (; i < max_num_reqs; i += nthreads) {
            int v = 0;
            if (i < num_reqs) {
                int qlen = __ldg(&qsl[i + 1]) - __ldg(&qsl[i]);
                v = __ldg(&nct[__ldg(&idx_mapping[i])]) + qlen;
            }
            seq_out[i] = (float)v;
        }
        return;
    }

    // ---- pos blocks: persistent over requests {bid, bid+POS_BLOCKS, ...}
    int r = bid;
    int s = 0, e = 0, nv = 0;
    bool valid = (r < num_reqs);
    if (valid) {
        s = __ldg(&qsl[r]);
        e = __ldg(&qsl[r + 1]);
        int im = __ldg(&idx_mapping[r]);
        nv = __ldg(&nct[im]);
    }

    while (valid) {
        // prefetch next request's metadata (chain overlaps current stores)
        const int rn = r + POS_BLOCKS;
        const bool vn = (rn < num_reqs);
        int sn = 0, en = 0, nvn = 0;
        if (vn) {
            sn = __ldg(&qsl[rn]);
            en = __ldg(&qsl[rn + 1]);
            int imn = __ldg(&idx_mapping[rn]);
            nvn = __ldg(&nct[imn]);
        }

        // stream current request [s, e)
        if (e > s) {
            const int base = nv - s;                 // pos[t] = base + t
            const int a0 = (s + 3) & ~3;
            const int a1 = e & ~3;
            if (a1 > a0) {
                int t = s + (int)threadIdx.x;
                if (t < a0) out_base[t] = (float)(base + t);

                const int nv4 = (a1 - a0) >> 2;
                float4* vp = reinterpret_cast<float4*>(out_base + a0);
                int v = (int)threadIdx.x;
                if (v < nv4) {
                    float f0 = (float)(a0 + (v << 2) + base);  // one I2F
                    unsigned long long lo = packf2(f0, f0 + 1.0f);
                    unsigned long long hi = packf2(f0 + 2.0f, f0 + 3.0f);
                    const unsigned long long inc = packf2(1024.0f, 1024.0f);
                    do {
                        *reinterpret_cast<ulonglong2*>(vp + v) =
                            make_ulonglong2(lo, hi);
                        lo = addf32x2(lo, inc);
                        hi = addf32x2(hi, inc);
                        v += 256;
                    } while (v < nv4);
                }

                int tt = a1 + (int)threadIdx.x;
                if (tt < e) out_base[tt] = (float)(base + tt);
            } else {
                for (int t = s + (int)threadIdx.x; t < e; t += 256)
                    out_base[t] = (float)(base + t);
            }
        }

        r = rn; s = sn; e = en; nv = nvn; valid = vn;
    }
}

extern "C" void kernel_launch(void* const* d_in, const int* in_sizes, int n_in,
                              void* d_out, int out_size) {
    // stable sort of input indices by size (ascending)
    int ord[32];
    int n = n_in > 32 ? 32 : n_in;
    for (int i = 0; i < n; i++) ord[i] = i;
    for (int i = 1; i < n; i++) {
        int key = ord[i];
        int j = i - 1;
        while (j >= 0 && in_sizes[ord[j]] > in_sizes[key]) {
            ord[j + 1] = ord[j];
            j--;
        }
        ord[j + 1] = key;
    }
    // rank mapping: ord[0]=idx_mapping, ord[1]=qsl, ord[2]=num_computed_tokens
    int idx_i = ord[0];
    int qsl_i = (n > 1) ? ord[1] : ord[0];
    int nct_i = (n > 2) ? ord[2] : qsl_i;

    const int* idx_mapping = (const int*)d_in[idx_i];
    const int* qsl         = (const int*)d_in[qsl_i];
    const int* nct         = (const int*)d_in[nct_i];

    // unit: size(qsl) - size(idx) == bytes-per-element of in_sizes
    long long unit = (long long)in_sizes[qsl_i] - (long long)in_sizes[idx_i];
    if (unit <= 0) unit = 1;
    const int num_reqs     = (int)(in_sizes[idx_i] / unit);
    const int max_num_reqs = (int)(in_sizes[nct_i] / unit);

    fused_fill_kernel<<<POS_BLOCKS + SEQ_BLOCKS, 256>>>(
        idx_mapping, qsl, nct, (float*)d_out,
        num_reqs, max_num_reqs, (long long)out_size);
}

// round 11
// speedup vs baseline: 1.3472x; 1.0361x over previous
#include <cuda_runtime.h>
#include <cstdint>

// Ragged position fill (vLLM prepare-inputs style).
//   pos[t]      = nct[idx_mapping[req(t)]] + (t - qsl[req(t)])   (= base + t)
//   seq_lens[r] = nct[idx_mapping[r]] + (qsl[r+1]-qsl[r]) for r<num_reqs, else 0
// d_out = [ pos (num_tokens) | seq_lens (max_num_reqs) ]  as FLOAT32.
//
// R11: four STG-based designs all plateaued at ~16.6us with nothing saturated
// -> per-SM L1tex store path is the shared binder. This version routes the
// bulk of the output through TMA bulk stores: values are built in SMEM
// (STS.128) and drained SMEM->L2 by the async copy engine
// (cp.async.bulk.global.shared::cta.bulk_group), double-buffered.

#define SEQ_BLOCKS 64
#define POS_BLOCKS 1184
#define CHUNK_FLOATS 2048          // 8KB per buffer, x2 buffers = 16KB smem
#define TMA_MIN_FLOATS 512         // bodies smaller than this use direct STG

__device__ __forceinline__ uint32_t smem_u32(const void* p) {
    uint32_t a;
    asm("{ .reg .u64 t; cvta.to.shared.u64 t, %1; cvt.u32.u64 %0, t; }"
        : "=r"(a) : "l"(p));
    return a;
}

__global__ __launch_bounds__(256) void fused_fill_kernel(
    const int* __restrict__ idx_mapping,
    const int* __restrict__ qsl,
    const int* __restrict__ nct,
    float* __restrict__ out_base,
    int num_reqs, int max_num_reqs,
    long long out_size)
{
    const int bid = (int)blockIdx.x;

    if (bid >= POS_BLOCKS) {
        // ---- seq_lens blocks: cover [0, max_num_reqs) ----
        const long long num_tokens = (long long)__ldg(&qsl[num_reqs]);
        const long long need = num_tokens + (long long)max_num_reqs;
        if (out_size != need && out_size != 4 * need) return;
        float* seq_out = out_base + num_tokens;
        const int nthreads = SEQ_BLOCKS * 256;
        int i = (bid - POS_BLOCKS) * 256 + (int)threadIdx.x;
        for (; i < max_num_reqs; i += nthreads) {
            int v = 0;
            if (i < num_reqs) {
                int qlen = __ldg(&qsl[i + 1]) - __ldg(&qsl[i]);
                v = __ldg(&nct[__ldg(&idx_mapping[i])]) + qlen;
            }
            seq_out[i] = (float)v;
        }
        return;
    }

    // ---- pos blocks: persistent over requests {bid, bid+POS_BLOCKS, ...} ----
    __shared__ __align__(16) float sbuf[2][CHUNK_FLOATS];
    const int tid = (int)threadIdx.x;
    int parity = 0;                 // persists across requests within a block

    for (int r = bid; r < num_reqs; r += POS_BLOCKS) {
        const int s  = __ldg(&qsl[r]);
        const int e  = __ldg(&qsl[r + 1]);
        if (e <= s) continue;
        const int im = __ldg(&idx_mapping[r]);
        const int base = __ldg(&nct[im]) - s;      // pos[t] = base + t

        const int a0 = (s + 3) & ~3;
        const int a1 = e & ~3;

        if (a1 - a0 >= TMA_MIN_FLOATS) {
            // head (<=3 elems)
            int t = s + tid;
            if (t < a0) out_base[t] = (float)(base + t);

            // body via SMEM + TMA bulk store, double-buffered
            int off = a0;
            while (off < a1) {
                int len = a1 - off;
                if (len > CHUNK_FLOATS) len = CHUNK_FLOATS;   // multiple of 4

                // gate buffer reuse: at most 1 outstanding bulk group
                if (tid == 0)
                    asm volatile("cp.async.bulk.wait_group.read 1;" ::: "memory");
                __syncthreads();

                float* b = sbuf[parity];
                for (int i = tid * 4; i < len; i += 1024) {
                    int tv = base + off + i;
                    *reinterpret_cast<float4*>(b + i) =
                        make_float4((float)tv, (float)(tv + 1),
                                    (float)(tv + 2), (float)(tv + 3));
                }
                __syncthreads();

                if (tid == 0) {
                    asm volatile("fence.proxy.async.shared::cta;" ::: "memory");
                    uint32_t saddr = smem_u32(b);
                    asm volatile(
                        "cp.async.bulk.global.shared::cta.bulk_group "
                        "[%0], [%1], %2;"
                        :: "l"(out_base + off), "r"(saddr), "r"(len * 4)
                        : "memory");
                    asm volatile("cp.async.bulk.commit_group;" ::: "memory");
                }
                off += len;
                parity ^= 1;
            }

            // tail (<=3 elems)
            int tt = a1 + tid;
            if (tt < e) out_base[tt] = (float)(base + tt);
        } else {
            // small span: direct STG path
            if (a1 > a0) {
                int t = s + tid;
                if (t < a0) out_base[t] = (float)(base + t);
                const int nv4 = (a1 - a0) >> 2;
                float4* vp = reinterpret_cast<float4*>(out_base + a0);
                for (int v = tid; v < nv4; v += 256) {
                    int tv = a0 + (v << 2) + base;
                    vp[v] = make_float4((float)tv, (float)(tv + 1),
                                        (float)(tv + 2), (float)(tv + 3));
                }
                int tt = a1 + tid;
                if (tt < e) out_base[tt] = (float)(base + tt);
            } else {
                for (int t = s + tid; t < e; t += 256)
                    out_base[t] = (float)(base + t);
            }
        }
    }

    // drain all outstanding bulk stores before exit
    if (tid == 0)
        asm volatile("cp.async.bulk.wait_group 0;" ::: "memory");
}

extern "C" void kernel_launch(void* const* d_in, const int* in_sizes, int n_in,
                              void* d_out, int out_size) {
    // stable sort of input indices by size (ascending)
    int ord[32];
    int n = n_in > 32 ? 32 : n_in;
    for (int i = 0; i < n; i++) ord[i] = i;
    for (int i = 1; i < n; i++) {
        int key = ord[i];
        int j = i - 1;
        while (j >= 0 && in_sizes[ord[j]] > in_sizes[key]) {
            ord[j + 1] = ord[j];
            j--;
        }
        ord[j + 1] = key;
    }
    // rank mapping: ord[0]=idx_mapping, ord[1]=qsl, ord[2]=num_computed_tokens
    int idx_i = ord[0];
    int qsl_i = (n > 1) ? ord[1] : ord[0];
    int nct_i = (n > 2) ? ord[2] : qsl_i;

    const int* idx_mapping = (const int*)d_in[idx_i];
    const int* qsl         = (const int*)d_in[qsl_i];
    const int* nct         = (const int*)d_in[nct_i];

    // unit: size(qsl) - size(idx) == bytes-per-element of in_sizes
    long long unit = (long long)in_sizes[qsl_i] - (long long)in_sizes[idx_i];
    if (unit <= 0) unit = 1;
    const int num_reqs     = (int)(in_sizes[idx_i] / unit);
    const int max_num_reqs = (int)(in_sizes[nct_i] / unit);

    fused_fill_kernel<<<POS_BLOCKS + SEQ_BLOCKS, 256>>>(
        idx_mapping, qsl, nct, (float*)d_out,
        num_reqs, max_num_reqs, (long long)out_size);
}